// round 3
// baseline (speedup 1.0000x reference)
#include <cuda_runtime.h>
#include <cuda_bf16.h>

#define N_NODES 100000
#define N_EDGES 1600000
#define D 128

// Scratch (device globals: allocation-free per harness rules)
__device__ float g_agg[N_NODES * D];   // 51.2 MB aggregated neighbor features
__device__ float g_deg[N_NODES];       // in-degree (as float)
__device__ int   g_is64;               // 1 if edge_index is int64, 0 if int32

// ---------------------------------------------------------------------------
// Kernel 0: detect index dtype. If buffer is int64 little-endian with values
// in [0, 2^31), every odd 32-bit word is 0. Random int32 indices in
// [0, 100000) are 0 with prob ~1e-5 each; 64 consecutive zeros => int64.
// Deterministic: same input buffer -> same flag every replay.
// ---------------------------------------------------------------------------
__global__ void detect_kernel(const int* __restrict__ ei32) {
    if (threadIdx.x == 0 && blockIdx.x == 0) {
        int allzero = 1;
        for (int i = 0; i < 64; i++)
            if (ei32[2 * i + 1] != 0) { allzero = 0; break; }
        g_is64 = allzero;
    }
}

// ---------------------------------------------------------------------------
// Kernel 1: zero the accumulators (must run every launch — graph replays)
// ---------------------------------------------------------------------------
__global__ void zero_kernel() {
    const int tot4 = N_NODES * D / 4;  // 3,200,000 float4s
    for (int i = blockIdx.x * blockDim.x + threadIdx.x; i < tot4;
         i += gridDim.x * blockDim.x) {
        ((float4*)g_agg)[i] = make_float4(0.f, 0.f, 0.f, 0.f);
        if (i < N_NODES) g_deg[i] = 0.f;
    }
}

// ---------------------------------------------------------------------------
// Kernel 2: edge gather/scatter. One warp per edge.
// agg[row] += x[col]  (vector red, no return)
// deg[row] += 1
// ---------------------------------------------------------------------------
__global__ void edge_kernel(const float* __restrict__ x,
                            const void* __restrict__ ei_raw) {
    int w = (blockIdx.x * blockDim.x + threadIdx.x) >> 5;
    if (w >= N_EDGES) return;
    int lane = threadIdx.x & 31;

    long long row, col;
    if (g_is64) {
        const long long* ei = (const long long*)ei_raw;
        row = ei[w];
        col = ei[N_EDGES + w];
    } else {
        const int* ei = (const int*)ei_raw;
        row = ei[w];
        col = ei[N_EDGES + w];
    }
    // Safety guard: never fault, even if dtype detection is wrong.
    if ((unsigned long long)row >= N_NODES || (unsigned long long)col >= N_NODES)
        return;

    const float4 v = *reinterpret_cast<const float4*>(x + col * D + lane * 4);
    float* dst = g_agg + row * D + lane * 4;
    asm volatile("red.global.add.v4.f32 [%0], {%1,%2,%3,%4};"
                 :: "l"(dst), "f"(v.x), "f"(v.y), "f"(v.z), "f"(v.w)
                 : "memory");
    if (lane == 0) atomicAdd(g_deg + row, 1.0f);
}

// ---------------------------------------------------------------------------
// Kernel 3: fused GEMM epilogue.
// out[i] = (agg[i]/max(deg[i],1)) @ W + x[i] @ root + bias
// z = [x[i] | agg[i]/deg] (256-wide) times M = [root; W] (256x128).
// Block: 64 rows x 128 cols, 256 threads, 8x4 register microtile per thread.
// Shared: M (256x128 = 128KB) + Z tile (64x256 = 64KB) = 192KB dynamic smem.
// ---------------------------------------------------------------------------
__global__ __launch_bounds__(256) void gemm_kernel(
    const float* __restrict__ x, const float* __restrict__ W,
    const float* __restrict__ R, const float* __restrict__ bias,
    float* __restrict__ out) {
    extern __shared__ float sm[];
    float* sM = sm;              // [256][128]: rows 0..127 = root, 128..255 = W
    float* sZ = sm + 256 * 128;  // [64][256]

    const int t = threadIdx.x;
    const int blockRow = blockIdx.x * 64;

    // Load combined weight matrix into shared (coalesced float4)
    for (int v = t; v < 8192; v += 256) {
        int k = v >> 5;
        int j = (v & 31) << 2;
        float4 val = (k < 128)
            ? *reinterpret_cast<const float4*>(R + k * 128 + j)
            : *reinterpret_cast<const float4*>(W + (k - 128) * 128 + j);
        *reinterpret_cast<float4*>(sM + k * 128 + j) = val;
    }
    // Load input tile: z = [x | agg * invdeg]
    for (int v = t; v < 4096; v += 256) {
        int i = v >> 6;
        int k = (v & 63) << 2;
        int gr = blockRow + i;
        float4 val = make_float4(0.f, 0.f, 0.f, 0.f);
        if (gr < N_NODES) {
            if (k < 128) {
                val = *reinterpret_cast<const float4*>(x + (long long)gr * D + k);
            } else {
                float invd = 1.0f / fmaxf(g_deg[gr], 1.0f);
                val = *reinterpret_cast<const float4*>(g_agg + (long long)gr * D + (k - 128));
                val.x *= invd; val.y *= invd; val.z *= invd; val.w *= invd;
            }
        }
        *reinterpret_cast<float4*>(sZ + i * 256 + k) = val;
    }
    __syncthreads();

    const int warp = t >> 5;   // row group (8 rows each) — uniform per warp
    const int lane = t & 31;   // col group (4 cols each)

    float acc[8][4];
#pragma unroll
    for (int i = 0; i < 8; i++)
#pragma unroll
        for (int c = 0; c < 4; c++) acc[i][c] = 0.f;

    for (int k = 0; k < 256; k += 4) {
        float4 m0 = *reinterpret_cast<float4*>(sM + (k + 0) * 128 + lane * 4);
        float4 m1 = *reinterpret_cast<float4*>(sM + (k + 1) * 128 + lane * 4);
        float4 m2 = *reinterpret_cast<float4*>(sM + (k + 2) * 128 + lane * 4);
        float4 m3 = *reinterpret_cast<float4*>(sM + (k + 3) * 128 + lane * 4);
#pragma unroll
        for (int i = 0; i < 8; i++) {
            float4 z = *reinterpret_cast<float4*>(sZ + (warp * 8 + i) * 256 + k);
            acc[i][0] += z.x * m0.x + z.y * m1.x + z.z * m2.x + z.w * m3.x;
            acc[i][1] += z.x * m0.y + z.y * m1.y + z.z * m2.y + z.w * m3.y;
            acc[i][2] += z.x * m0.z + z.y * m1.z + z.z * m2.z + z.w * m3.z;
            acc[i][3] += z.x * m0.w + z.y * m1.w + z.z * m2.w + z.w * m3.w;
        }
    }

    const float4 b = *reinterpret_cast<const float4*>(bias + lane * 4);
#pragma unroll
    for (int i = 0; i < 8; i++) {
        int gr = blockRow + warp * 8 + i;
        if (gr < N_NODES) {
            float4 o = make_float4(acc[i][0] + b.x, acc[i][1] + b.y,
                                   acc[i][2] + b.z, acc[i][3] + b.w);
            *reinterpret_cast<float4*>(out + (long long)gr * D + lane * 4) = o;
        }
    }
}

// ---------------------------------------------------------------------------
extern "C" void kernel_launch(void* const* d_in, const int* in_sizes, int n_in,
                              void* d_out, int out_size) {
    const float* x    = (const float*)d_in[0];
    const void*  ei   = d_in[1];
    const float* W    = (const float*)d_in[2];
    const float* R    = (const float*)d_in[3];
    const float* bias = (const float*)d_in[4];
    float*       out  = (float*)d_out;

    // 0. detect index dtype (int32 vs int64)
    detect_kernel<<<1, 32>>>((const int*)ei);

    // 1. zero accumulators
    zero_kernel<<<2048, 256>>>();

    // 2. edge scatter: one warp per edge
    {
        long long threads = (long long)N_EDGES * 32;
        int blocks = (int)((threads + 255) / 256);
        edge_kernel<<<blocks, 256>>>(x, ei);
    }

    // 3. fused GEMM epilogue
    {
        const int SMEM = (256 * 128 + 64 * 256) * sizeof(float);  // 192 KB
        cudaFuncSetAttribute(gemm_kernel,
                             cudaFuncAttributeMaxDynamicSharedMemorySize, SMEM);
        int blocks = (N_NODES + 63) / 64;
        gemm_kernel<<<blocks, 256, SMEM>>>(x, W, R, bias, out);
    }
}

// round 4
// speedup vs baseline: 1.0815x; 1.0815x over previous
#include <cuda_runtime.h>
#include <cuda_bf16.h>

#define N_NODES 100000
#define N_EDGES 1600000
#define D 128

#define GW 24                 // warps per gemm CTA
#define GT (GW * 32)          // 768 threads
#define RPW 8                 // rows per warp
#define RPC (GW * RPW)        // 192 rows per CTA

// Scratch (device globals: allocation-free per harness rules)
__device__ float g_agg[N_NODES * D];   // 51.2 MB aggregated neighbor features
__device__ float g_deg[N_NODES];       // in-degree (as float)
__device__ int   g_is64;               // 1 if edge_index is int64, 0 if int32

// ---------------------------------------------------------------------------
// Kernel 0: detect index dtype (int64 little-endian in-range => odd words 0).
// ---------------------------------------------------------------------------
__global__ void detect_kernel(const int* __restrict__ ei32) {
    if (threadIdx.x == 0 && blockIdx.x == 0) {
        int allzero = 1;
        for (int i = 0; i < 64; i++)
            if (ei32[2 * i + 1] != 0) { allzero = 0; break; }
        g_is64 = allzero;
    }
}

// ---------------------------------------------------------------------------
// Kernel 1: zero the accumulators (graph replays -> must run every launch)
// ---------------------------------------------------------------------------
__global__ void zero_kernel() {
    const int tot4 = N_NODES * D / 4;
    for (int i = blockIdx.x * blockDim.x + threadIdx.x; i < tot4;
         i += gridDim.x * blockDim.x) {
        ((float4*)g_agg)[i] = make_float4(0.f, 0.f, 0.f, 0.f);
        if (i < N_NODES) g_deg[i] = 0.f;
    }
}

// ---------------------------------------------------------------------------
// Kernel 2: edge gather/scatter. One warp per edge.
// ---------------------------------------------------------------------------
__global__ void edge_kernel(const float* __restrict__ x,
                            const void* __restrict__ ei_raw) {
    int w = (blockIdx.x * blockDim.x + threadIdx.x) >> 5;
    if (w >= N_EDGES) return;
    int lane = threadIdx.x & 31;

    long long row, col;
    if (g_is64) {
        const long long* ei = (const long long*)ei_raw;
        row = ei[w];
        col = ei[N_EDGES + w];
    } else {
        const int* ei = (const int*)ei_raw;
        row = ei[w];
        col = ei[N_EDGES + w];
    }
    if ((unsigned long long)row >= N_NODES || (unsigned long long)col >= N_NODES)
        return;

    const float4 v = *reinterpret_cast<const float4*>(x + col * D + lane * 4);
    float* dst = g_agg + row * D + lane * 4;
    asm volatile("red.global.add.v4.f32 [%0], {%1,%2,%3,%4};"
                 :: "l"(dst), "f"(v.x), "f"(v.y), "f"(v.z), "f"(v.w)
                 : "memory");
    if (lane == 0) atomicAdd(g_deg + row, 1.0f);
}

// ---------------------------------------------------------------------------
// Kernel 3: fused GEMM.  out = invd*(agg @ W) + x @ R + bias
// Weights only in smem (128 KB). Z rows read as warp-uniform broadcast LDGs
// (all lanes of a warp share the same 8 rows; lanes differ only in column).
// 768 threads, 24 warps, 8 rows/warp, 4 cols/lane -> 192x128 tile per CTA.
// agg-half accumulated first, scaled by invd once, then x-half into same acc.
// ---------------------------------------------------------------------------
__global__ __launch_bounds__(GT, 1) void gemm_kernel(
    const float* __restrict__ x, const float* __restrict__ W,
    const float* __restrict__ R, const float* __restrict__ bias,
    float* __restrict__ out) {
    extern __shared__ float sm[];   // [256][128]: rows 0..127 = W, 128..255 = R
    float4* sm4 = (float4*)sm;

    const int t = threadIdx.x;

    // Load weights: W into k=0..127, R into k=128..255 (coalesced float4)
    for (int v = t; v < 8192; v += GT) {
        int k = v >> 5;
        int j = v & 31;
        float4 val = (k < 128)
            ? *reinterpret_cast<const float4*>(W + k * 128 + j * 4)
            : *reinterpret_cast<const float4*>(R + (k - 128) * 128 + j * 4);
        sm4[k * 32 + j] = val;
    }
    __syncthreads();

    const int warp = t >> 5;
    const int lane = t & 31;
    const int row0 = blockIdx.x * RPC + warp * RPW;

    // Clamped row indices (OOB rows compute garbage, never stored)
    int gri[RPW];
#pragma unroll
    for (int i = 0; i < RPW; i++) {
        int gr = row0 + i;
        gri[i] = gr < N_NODES ? gr : N_NODES - 1;
    }

    float acc[RPW][4];
#pragma unroll
    for (int i = 0; i < RPW; i++)
#pragma unroll
        for (int c = 0; c < 4; c++) acc[i][c] = 0.f;

    // ---- half 1: agg @ W ----
#pragma unroll 2
    for (int k = 0; k < 128; k += 4) {
        float4 m0 = sm4[(k + 0) * 32 + lane];
        float4 m1 = sm4[(k + 1) * 32 + lane];
        float4 m2 = sm4[(k + 2) * 32 + lane];
        float4 m3 = sm4[(k + 3) * 32 + lane];
#pragma unroll
        for (int i = 0; i < RPW; i++) {
            float4 z = __ldg((const float4*)(g_agg + (long long)gri[i] * D + k));
            acc[i][0] += z.x * m0.x + z.y * m1.x + z.z * m2.x + z.w * m3.x;
            acc[i][1] += z.x * m0.y + z.y * m1.y + z.z * m2.y + z.w * m3.y;
            acc[i][2] += z.x * m0.z + z.y * m1.z + z.z * m2.z + z.w * m3.z;
            acc[i][3] += z.x * m0.w + z.y * m1.w + z.z * m2.w + z.w * m3.w;
        }
    }

    // ---- scale by 1/deg ----
#pragma unroll
    for (int i = 0; i < RPW; i++) {
        float invd = 1.0f / fmaxf(__ldg(g_deg + gri[i]), 1.0f);
        acc[i][0] *= invd; acc[i][1] *= invd;
        acc[i][2] *= invd; acc[i][3] *= invd;
    }

    // ---- half 2: x @ R ----
#pragma unroll 2
    for (int k = 0; k < 128; k += 4) {
        float4 m0 = sm4[(k + 128) * 32 + lane];
        float4 m1 = sm4[(k + 129) * 32 + lane];
        float4 m2 = sm4[(k + 130) * 32 + lane];
        float4 m3 = sm4[(k + 131) * 32 + lane];
#pragma unroll
        for (int i = 0; i < RPW; i++) {
            float4 z = __ldg((const float4*)(x + (long long)gri[i] * D + k));
            acc[i][0] += z.x * m0.x + z.y * m1.x + z.z * m2.x + z.w * m3.x;
            acc[i][1] += z.x * m0.y + z.y * m1.y + z.z * m2.y + z.w * m3.y;
            acc[i][2] += z.x * m0.z + z.y * m1.z + z.z * m2.z + z.w * m3.z;
            acc[i][3] += z.x * m0.w + z.y * m1.w + z.z * m2.w + z.w * m3.w;
        }
    }

    // ---- epilogue ----
    const float4 b = *reinterpret_cast<const float4*>(bias + lane * 4);
#pragma unroll
    for (int i = 0; i < RPW; i++) {
        int gr = row0 + i;
        if (gr < N_NODES) {
            float4 o = make_float4(acc[i][0] + b.x, acc[i][1] + b.y,
                                   acc[i][2] + b.z, acc[i][3] + b.w);
            *reinterpret_cast<float4*>(out + (long long)gr * D + lane * 4) = o;
        }
    }
}

// ---------------------------------------------------------------------------
extern "C" void kernel_launch(void* const* d_in, const int* in_sizes, int n_in,
                              void* d_out, int out_size) {
    const float* x    = (const float*)d_in[0];
    const void*  ei   = d_in[1];
    const float* W    = (const float*)d_in[2];
    const float* R    = (const float*)d_in[3];
    const float* bias = (const float*)d_in[4];
    float*       out  = (float*)d_out;

    detect_kernel<<<1, 32>>>((const int*)ei);
    zero_kernel<<<2048, 256>>>();

    {
        long long threads = (long long)N_EDGES * 32;
        int blocks = (int)((threads + 255) / 256);
        edge_kernel<<<blocks, 256>>>(x, ei);
    }

    {
        const int SMEM = 256 * 128 * sizeof(float);  // 128 KB (weights only)
        cudaFuncSetAttribute(gemm_kernel,
                             cudaFuncAttributeMaxDynamicSharedMemorySize, SMEM);
        int blocks = (N_NODES + RPC - 1) / RPC;      // 521
        gemm_kernel<<<blocks, GT, SMEM>>>(x, W, R, bias, out);
    }
}

// round 6
// speedup vs baseline: 1.6821x; 1.5553x over previous
#include <cuda_runtime.h>
#include <cuda_bf16.h>
#include <cstdint>

#define N_NODES 100000
#define N_EDGES 1600000
#define D 128

// ---------------- scratch (device globals; no allocation) -------------------
__device__ float g_agg[N_NODES * D];
__device__ float g_deg[N_NODES];
__device__ int   g_is64;

__device__ __forceinline__ uint32_t f2tf32(float f) {
    uint32_t r;
    asm("cvt.rna.tf32.f32 %0, %1;" : "=r"(r) : "f"(f));
    return r;
}

// ---------------------------------------------------------------------------
__global__ void detect_kernel(const int* __restrict__ ei32) {
    if (threadIdx.x == 0 && blockIdx.x == 0) {
        int allzero = 1;
        for (int i = 0; i < 64; i++)
            if (ei32[2 * i + 1] != 0) { allzero = 0; break; }
        g_is64 = allzero;
    }
}

__global__ void zero_kernel() {
    const int tot4 = N_NODES * D / 4;
    for (int i = blockIdx.x * blockDim.x + threadIdx.x; i < tot4;
         i += gridDim.x * blockDim.x) {
        ((float4*)g_agg)[i] = make_float4(0.f, 0.f, 0.f, 0.f);
        if (i < N_NODES) g_deg[i] = 0.f;
    }
}

__global__ void edge_kernel(const float* __restrict__ x,
                            const void* __restrict__ ei_raw) {
    int w = (blockIdx.x * blockDim.x + threadIdx.x) >> 5;
    if (w >= N_EDGES) return;
    int lane = threadIdx.x & 31;

    long long row, col;
    if (g_is64) {
        const long long* ei = (const long long*)ei_raw;
        row = ei[w]; col = ei[N_EDGES + w];
    } else {
        const int* ei = (const int*)ei_raw;
        row = ei[w]; col = ei[N_EDGES + w];
    }
    if ((unsigned long long)row >= N_NODES || (unsigned long long)col >= N_NODES)
        return;

    const float4 v = *reinterpret_cast<const float4*>(x + col * D + lane * 4);
    float* dst = g_agg + row * D + lane * 4;
    asm volatile("red.global.add.v4.f32 [%0], {%1,%2,%3,%4};"
                 :: "l"(dst), "f"(v.x), "f"(v.y), "f"(v.z), "f"(v.w) : "memory");
    if (lane == 0) atomicAdd(g_deg + row, 1.0f);
}

// ---------------------------------------------------------------------------
// GEMM via mma.sync.m16n8k8 tf32 (legacy tensor path, works on plain sm_100).
// out = x @ R + (invd*agg) @ W + bias, fused as two K=128 phases into one
// accumulator set. CTA: 512 thr = 16 warps (4m x 4n), tile 128x128,
// warp tile 32x32. SMEM: A[128][132] + B[132*128] tf32, pad-132 makes both
// fragment load patterns bank-conflict-free.
// ---------------------------------------------------------------------------
#define PAD 132
#define SM_FLOATS (2 * 128 * PAD)

__global__ __launch_bounds__(512, 1) void gemm_mma(
    const float* __restrict__ x, const float* __restrict__ W,
    const float* __restrict__ R, const float* __restrict__ bias,
    float* __restrict__ out) {
    extern __shared__ float sm[];
    uint32_t* sA = (uint32_t*)sm;               // [128][PAD] A tile (tf32 bits)
    uint32_t* sB = (uint32_t*)(sm + 128 * PAD); // [128][PAD] B tile: B[k][n]

    const int t = threadIdx.x;
    const int wid = t >> 5;
    const int lane = t & 31;
    const int wm = wid >> 2;   // warp row 0..3
    const int wn = wid & 3;    // warp col 0..3
    const int row0 = blockIdx.x * 128;

    float c[2][4][4];
#pragma unroll
    for (int mt = 0; mt < 2; mt++)
#pragma unroll
        for (int nt = 0; nt < 4; nt++)
#pragma unroll
            for (int e = 0; e < 4; e++) c[mt][nt][e] = 0.f;

    for (int h = 0; h < 2; h++) {
        const float* Asrc = h ? g_agg : x;
        const float* Bsrc = h ? W : R;

        // ---- stage A (rows of x or invd*agg) and B (R or W, [k][n]) ----
        for (int v = t; v < 4096; v += 512) {
            int r  = v >> 5;          // A row / B k-row
            int k4 = (v & 31) << 2;   // col group
            int gr = row0 + r; if (gr >= N_NODES) gr = N_NODES - 1;

            float4 av = *reinterpret_cast<const float4*>(Asrc + (long long)gr * D + k4);
            if (h) {
                float invd = 1.0f / fmaxf(g_deg[gr], 1.0f);
                av.x *= invd; av.y *= invd; av.z *= invd; av.w *= invd;
            }
            uint4 ap = make_uint4(f2tf32(av.x), f2tf32(av.y), f2tf32(av.z), f2tf32(av.w));
            *reinterpret_cast<uint4*>(sA + r * PAD + k4) = ap;

            float4 bv = *reinterpret_cast<const float4*>(Bsrc + r * 128 + k4);
            uint4 bp = make_uint4(f2tf32(bv.x), f2tf32(bv.y), f2tf32(bv.z), f2tf32(bv.w));
            *reinterpret_cast<uint4*>(sB + r * PAD + k4) = bp;
        }
        __syncthreads();

        // ---- compute: 16 k-chunks of 8 ----
        const int lr = lane >> 2;   // 0..7
        const int lk = lane & 3;    // 0..3
        const int arow = wm * 32 + lr;
        const int bn   = wn * 32 + lr;
#pragma unroll
        for (int kc = 0; kc < 16; kc++) {
            const int kb = kc * 8;
            uint32_t a[2][4];
#pragma unroll
            for (int mt = 0; mt < 2; mt++) {
                int r_ = arow + mt * 16;
                a[mt][0] = sA[(r_    ) * PAD + kb + lk];
                a[mt][1] = sA[(r_ + 8) * PAD + kb + lk];
                a[mt][2] = sA[(r_    ) * PAD + kb + lk + 4];
                a[mt][3] = sA[(r_ + 8) * PAD + kb + lk + 4];
            }
            uint32_t b[4][2];
#pragma unroll
            for (int nt = 0; nt < 4; nt++) {
                b[nt][0] = sB[(kb + lk    ) * PAD + bn + nt * 8];
                b[nt][1] = sB[(kb + lk + 4) * PAD + bn + nt * 8];
            }
#pragma unroll
            for (int mt = 0; mt < 2; mt++)
#pragma unroll
                for (int nt = 0; nt < 4; nt++) {
                    asm volatile(
                        "mma.sync.aligned.m16n8k8.row.col.f32.tf32.tf32.f32 "
                        "{%0,%1,%2,%3}, {%4,%5,%6,%7}, {%8,%9}, {%0,%1,%2,%3};"
                        : "+f"(c[mt][nt][0]), "+f"(c[mt][nt][1]),
                          "+f"(c[mt][nt][2]), "+f"(c[mt][nt][3])
                        : "r"(a[mt][0]), "r"(a[mt][1]), "r"(a[mt][2]), "r"(a[mt][3]),
                          "r"(b[nt][0]), "r"(b[nt][1]));
                }
        }
        __syncthreads();
    }

    // ---- epilogue: bias + store ----
    const int lr = lane >> 2;
    const int lq = lane & 3;
#pragma unroll
    for (int mt = 0; mt < 2; mt++) {
#pragma unroll
        for (int nt = 0; nt < 4; nt++) {
            int cb = wn * 32 + nt * 8 + lq * 2;
            float2 bb = *reinterpret_cast<const float2*>(bias + cb);
            int r0 = row0 + wm * 32 + mt * 16 + lr;
            if (r0 < N_NODES) {
                float2 o = make_float2(c[mt][nt][0] + bb.x, c[mt][nt][1] + bb.y);
                *reinterpret_cast<float2*>(out + (long long)r0 * D + cb) = o;
            }
            int r1 = r0 + 8;
            if (r1 < N_NODES) {
                float2 o = make_float2(c[mt][nt][2] + bb.x, c[mt][nt][3] + bb.y);
                *reinterpret_cast<float2*>(out + (long long)r1 * D + cb) = o;
            }
        }
    }
}

// ---------------------------------------------------------------------------
extern "C" void kernel_launch(void* const* d_in, const int* in_sizes, int n_in,
                              void* d_out, int out_size) {
    const float* x    = (const float*)d_in[0];
    const void*  ei   = d_in[1];
    const float* W    = (const float*)d_in[2];
    const float* R    = (const float*)d_in[3];
    const float* bias = (const float*)d_in[4];
    float*       out  = (float*)d_out;

    detect_kernel<<<1, 32>>>((const int*)ei);
    zero_kernel<<<2048, 256>>>();

    {
        long long threads = (long long)N_EDGES * 32;
        int blocks = (int)((threads + 255) / 256);
        edge_kernel<<<blocks, 256>>>(x, ei);
    }

    {
        const int SMEM = SM_FLOATS * sizeof(float);   // 135,168 B
        cudaFuncSetAttribute(gemm_mma,
                             cudaFuncAttributeMaxDynamicSharedMemorySize, SMEM);
        int blocks = (N_NODES + 127) / 128;           // 782
        gemm_mma<<<blocks, 512, SMEM>>>(x, W, R, bias, out);
    }
}